// round 3
// baseline (speedup 1.0000x reference)
#include <cuda_runtime.h>
#include <cuda_bf16.h>

// BayesianMF: per-user Bayesian linear update
//   prec_u = lambda_K + alpha * sum_{j in obs(u)} V_j V_j^T
//   rhs_u  = alpha * sum_j r_j V_j + lambda_K @ mu_K
//   mu_u   = prec_u^{-1} rhs_u
//   L_u    = chol(prec_u^{-1})       (lower, positive diag)
//   out_u  = mu_u + L_u @ z_u
//
// chol(P^{-1}) identity: with J the reversal permutation, Q = J P J,
// H = chol(Q) lower. Then L = J H^{-T} J is lower-triangular with positive
// diagonal and L L^T = P^{-1}, so L = chol(P^{-1}) by uniqueness.
// Therefore L z = J H^{-T} (J z): ONE backward substitution, no explicit
// inverse and no second Cholesky.

#define D          16
#define NTRI       136          // 16*17/2
#define ACC_STRIDE 152          // 136 outer + 16 scoresum  (= 38 float4)
#define MAX_USERS  50000
#define ALPHA_F    2.0f

// tri(i,j) valid for i >= j
#define TRI(i, j) (((i) * ((i) + 1)) / 2 + (j))

// Scratch accumulators (no cudaMalloc allowed): 50000 * 152 * 4B = 30.4 MB
// 16B-aligned; ACC_STRIDE*4 = 608 bytes = 38*16 -> every user row is 16B-aligned.
__device__ __align__(16) float g_acc[(size_t)MAX_USERS * ACC_STRIDE];

// Vector f32 reduction (sm_90+): one REDG.128 instead of 4 scalar REDG.
__device__ __forceinline__ void red4(float* p, float a, float b, float c, float d) {
    asm volatile("red.global.add.v4.f32 [%0], {%1, %2, %3, %4};"
                 :: "l"(p), "f"(a), "f"(b), "f"(c), "f"(d) : "memory");
}

// ---------------------------------------------------------------------------
// Phase 0: zero the accumulators (float4 stores)
// ---------------------------------------------------------------------------
__global__ void zero_acc_kernel(int total4) {
    int i = blockIdx.x * blockDim.x + threadIdx.x;
    if (i < total4) {
        reinterpret_cast<float4*>(g_acc)[i] = make_float4(0.f, 0.f, 0.f, 0.f);
    }
}

// ---------------------------------------------------------------------------
// Phase 1: scatter-accumulate outer products + weighted scores.
// 38 x red.global.add.v4.f32 per observation (vs 152 scalar atomics).
// ---------------------------------------------------------------------------
__global__ void scatter_kernel(const float* __restrict__ V,
                               const float* __restrict__ ratings,
                               const int*   __restrict__ user_ids,
                               const int*   __restrict__ item_ids,
                               int nnz) {
    int j = blockIdx.x * blockDim.x + threadIdx.x;
    if (j >= nnz) return;

    const int u  = user_ids[j];
    const int it = item_ids[j];
    const float r = ratings[j];

    // V row: 64 contiguous bytes -> 4x float4 (V is 1.28MB, L2-resident)
    const float4* Vr = reinterpret_cast<const float4*>(V + (size_t)it * D);
    float4 a = Vr[0], b = Vr[1], c = Vr[2], dd = Vr[3];
    float v[D] = {a.x, a.y, a.z, a.w, b.x, b.y, b.z, b.w,
                  c.x, c.y, c.z, c.w, dd.x, dd.y, dd.z, dd.w};

    float* acc = g_acc + (size_t)u * ACC_STRIDE;

    // Emit the 152 dense contributions in packed order, flushing every 4
    // as one vector reduction. Fully unrolled: e is compile-time constant.
    float buf0, buf1, buf2, buf3;
    int e = 0;
#pragma unroll
    for (int i = 0; i < D; i++) {
#pragma unroll
        for (int k = 0; k <= i; k++) {
            const float val = v[i] * v[k];
            switch (e & 3) {
                case 0: buf0 = val; break;
                case 1: buf1 = val; break;
                case 2: buf2 = val; break;
                default:
                    buf3 = val;
                    red4(acc + (e - 3), buf0, buf1, buf2, buf3);
            }
            e++;
        }
    }
    // 136 % 4 == 0: score entries start on a fresh 16B group
#pragma unroll
    for (int i = 0; i < D; i++) {
        const float val = r * v[i];
        switch (e & 3) {
            case 0: buf0 = val; break;
            case 1: buf1 = val; break;
            case 2: buf2 = val; break;
            default:
                buf3 = val;
                red4(acc + (e - 3), buf0, buf1, buf2, buf3);
        }
        e++;
    }
}

// ---------------------------------------------------------------------------
// Phase 2: per-user dense solve (one thread per user, fully unrolled d=16)
// ---------------------------------------------------------------------------
__global__ void solve_kernel(const float* __restrict__ lambdaK,
                             const float* __restrict__ muK,
                             const float* __restrict__ z,
                             float*       __restrict__ out,
                             int num_users) {
    int u = blockIdx.x * blockDim.x + threadIdx.x;
    if (u >= num_users) return;

    const float* S = g_acc + (size_t)u * ACC_STRIDE;

    // Build Q = J * prec * J, packed lower (i >= j):
    //   Q[i][j] = prec[15-i][15-j]; with a=15-i <= b=15-j,
    //   prec[a][b] = lambda[a*16+b] + alpha * outer[b][a] (outer lower-packed)
    float H[NTRI];
#pragma unroll
    for (int i = 0; i < D; i++) {
#pragma unroll
        for (int j = 0; j <= i; j++) {
            const int a = 15 - i, b = 15 - j;   // b >= a
            H[TRI(i, j)] = __ldg(&lambdaK[a * D + b]) + ALPHA_F * S[TRI(b, a)];
        }
    }

    // Reversed rhs: w[i] = rhs[15-i], rhs[a] = alpha*score[a] + (lambda@muK)[a]
    float w[D];
#pragma unroll
    for (int i = 0; i < D; i++) {
        const int a = 15 - i;
        float t = ALPHA_F * S[NTRI + a];
#pragma unroll
        for (int b = 0; b < D; b++) {
            t += __ldg(&lambdaK[a * D + b]) * __ldg(&muK[b]);
        }
        w[i] = t;
    }

    // In-place Cholesky of Q: H becomes lower-triangular factor
    float dinv[D];
#pragma unroll
    for (int j = 0; j < D; j++) {
        float s = H[TRI(j, j)];
#pragma unroll
        for (int k = 0; k < j; k++) {
            const float g = H[TRI(j, k)];
            s -= g * g;
        }
        const float sq = sqrtf(s);
        const float rj = 1.0f / sq;
        H[TRI(j, j)] = sq;
        dinv[j] = rj;
#pragma unroll
        for (int i = j + 1; i < D; i++) {
            float t = H[TRI(i, j)];
#pragma unroll
            for (int k = 0; k < j; k++) {
                t -= H[TRI(i, k)] * H[TRI(j, k)];
            }
            H[TRI(i, j)] = t * rj;
        }
    }

    // Solve Q x = w: forward (H y = w) then backward (H^T x = y), in place.
    // Afterwards mu[a] = w[15-a].
#pragma unroll
    for (int i = 0; i < D; i++) {
        float t = w[i];
#pragma unroll
        for (int k = 0; k < i; k++) {
            t -= H[TRI(i, k)] * w[k];
        }
        w[i] = t * dinv[i];
    }
#pragma unroll
    for (int i = D - 1; i >= 0; i--) {
        float t = w[i];
#pragma unroll
        for (int k = D - 1; k > i; k--) {
            t -= H[TRI(k, i)] * w[k];
        }
        w[i] = t * dinv[i];
    }

    // Sample term: L z = J H^{-T} (J z). Load z reversed, backward-solve
    // H^T s = (Jz), then (Lz)[a] = s[15-a].
    const float4* zr = reinterpret_cast<const float4*>(z + (size_t)u * D);
    float4 z0 = zr[0], z1 = zr[1], z2 = zr[2], z3 = zr[3];
    float zf[D] = {z0.x, z0.y, z0.z, z0.w, z1.x, z1.y, z1.z, z1.w,
                   z2.x, z2.y, z2.z, z2.w, z3.x, z3.y, z3.z, z3.w};
    float s[D];
#pragma unroll
    for (int i = 0; i < D; i++) s[i] = zf[15 - i];   // Jz
#pragma unroll
    for (int i = D - 1; i >= 0; i--) {
        float t = s[i];
#pragma unroll
        for (int k = D - 1; k > i; k--) {
            t -= H[TRI(k, i)] * s[k];
        }
        s[i] = t * dinv[i];
    }

    // out[a] = mu[a] + (Lz)[a] = w[15-a] + s[15-a]
    float4* o = reinterpret_cast<float4*>(out + (size_t)u * D);
    float r0[D];
#pragma unroll
    for (int a = 0; a < D; a++) r0[a] = w[15 - a] + s[15 - a];
    o[0] = make_float4(r0[0],  r0[1],  r0[2],  r0[3]);
    o[1] = make_float4(r0[4],  r0[5],  r0[6],  r0[7]);
    o[2] = make_float4(r0[8],  r0[9],  r0[10], r0[11]);
    o[3] = make_float4(r0[12], r0[13], r0[14], r0[15]);
}

// ---------------------------------------------------------------------------
extern "C" void kernel_launch(void* const* d_in, const int* in_sizes, int n_in,
                              void* d_out, int out_size) {
    const float* V       = (const float*)d_in[0];
    const float* ratings = (const float*)d_in[1];
    const float* muK     = (const float*)d_in[2];
    const float* lambdaK = (const float*)d_in[3];
    const float* z       = (const float*)d_in[4];
    const int*   uid     = (const int*)d_in[5];
    const int*   iid     = (const int*)d_in[6];

    const int nnz       = in_sizes[5];        // user_ids length
    const int num_users = in_sizes[4] / D;    // z is [U, 16]

    const int total4 = num_users * ACC_STRIDE / 4;
    zero_acc_kernel<<<(total4 + 255) / 256, 256>>>(total4);
    scatter_kernel<<<(nnz + 255) / 256, 256>>>(V, ratings, uid, iid, nnz);
    solve_kernel<<<(num_users + 127) / 128, 128>>>(lambdaK, muK, z,
                                                   (float*)d_out, num_users);
}

// round 5
// speedup vs baseline: 1.0916x; 1.0916x over previous
#include <cuda_runtime.h>
#include <cuda_bf16.h>

// BayesianMF: per-user Bayesian linear update
//   prec_u = lambda_K + alpha * sum_{j in obs(u)} V_j V_j^T
//   rhs_u  = alpha * sum_j r_j V_j + lambda_K @ mu_K
//   mu_u   = prec_u^{-1} rhs_u ;  L_u = chol(prec_u^{-1}) ; out = mu + L z
//
// chol(P^{-1}) identity: J = reversal permutation, Q = J P J, H = chol(Q).
// Then L = J H^{-T} J = chol(P^{-1}), so L z = J H^{-T} (J z): one backward
// substitution, no explicit inverse, no second Cholesky.
//
// R5 = R4 with the off-diagonal block enumeration bug fixed (B = m-1 for
// m in {3,4}; R4 used m-2, which skipped block (1,3) and emitted invalid
// TRI(i<j) indices -> non-SPD matrices -> NaN).

#define D          16
#define NTRI       136          // 16*17/2
#define ACC_STRIDE 152          // 136 outer + 16 scoresum
#define MAX_USERS  50016
#define NNZ_MAX    1048576
#define ALPHA_F    2.0f

#define TRI(i, j) (((i) * ((i) + 1)) / 2 + (j))

// Scratch (no cudaMalloc allowed)
__device__ __align__(16) float g_acc[(size_t)MAX_USERS * ACC_STRIDE];  // 30.4 MB
__device__ int  g_counts[MAX_USERS];
__device__ int  g_offsets[MAX_USERS];
__device__ int  g_cursors[MAX_USERS];
__device__ int2 g_sorted[NNZ_MAX];                                     // 8 MB

// ---------------------------------------------------------------------------
// Phase 1a: zero per-user counts
// ---------------------------------------------------------------------------
__global__ void zero_counts_kernel(int num_users) {
    int i = blockIdx.x * blockDim.x + threadIdx.x;
    if (i < num_users) g_counts[i] = 0;
}

// Phase 1b: histogram of user_ids
__global__ void hist_kernel(const int* __restrict__ user_ids, int nnz) {
    int i = blockIdx.x * blockDim.x + threadIdx.x;
    if (i < nnz) atomicAdd(&g_counts[user_ids[i]], 1);
}

// Phase 1c: exclusive scan of counts (single block, 1024 threads)
__global__ void scan_kernel(int num_users) {
    __shared__ int sh[1024];
    const int tid = threadIdx.x;
    const int chunk = (num_users + 1023) >> 10;
    const int base = tid * chunk;

    int s = 0;
    for (int j = 0; j < chunk; j++) {
        int idx = base + j;
        if (idx < num_users) s += g_counts[idx];
    }
    sh[tid] = s;
    __syncthreads();
    // Hillis-Steele inclusive scan
    for (int off = 1; off < 1024; off <<= 1) {
        int val = (tid >= off) ? sh[tid - off] : 0;
        __syncthreads();
        sh[tid] += val;
        __syncthreads();
    }
    int excl = sh[tid] - s;
    for (int j = 0; j < chunk; j++) {
        int idx = base + j;
        if (idx < num_users) {
            g_offsets[idx] = excl;
            g_cursors[idx] = excl;
            excl += g_counts[idx];
        }
    }
}

// Phase 1d: bucket observations into CSR order (item id + rating packed)
__global__ void bucket_kernel(const int*   __restrict__ user_ids,
                              const int*   __restrict__ item_ids,
                              const float* __restrict__ ratings,
                              int nnz) {
    int i = blockIdx.x * blockDim.x + threadIdx.x;
    if (i >= nnz) return;
    int u = user_ids[i];
    int pos = atomicAdd(&g_cursors[u], 1);
    g_sorted[pos] = make_int2(item_ids[i], __float_as_int(ratings[i]));
}

// ---------------------------------------------------------------------------
// Phase 2: warp-per-user accumulation of outer product + score.
// Lane mapping (clique decomposition of the 136-entry lower triangle):
//   lanes 0..3  ("TT"): two 2x2 triangles (rows {4t,4t+1} and {4t+2,4t+3})
//                       -> 6 entries from 4 shuffled values
//   lanes 4..31 ("Q") : a full 2x2 block -> 4 entries from 4 shuffled values
//     c = lane-4; c<4: diag block d=c: rows {4d+2,4d+3} x cols {4d,4d+1}
//     c>=4: off-diag block m=(c-4)>>2 in {(0,1),(0,2),(0,3),(1,2),(1,3),(2,3)},
//           quadrant q=(c-4)&3: rows {4B+2(q>>1),+1} x cols {4A+2(q&1),+1}
//   lanes 4..19 additionally carry score entry d = lane-4 (r * v[d]).
// Per observation: 7 SHFL + ~11 FMA + 1 LDG (V row is L2-resident).
// ---------------------------------------------------------------------------
__global__ void accum_kernel(const float* __restrict__ V, int num_users) {
    const int gw   = (blockIdx.x * blockDim.x + threadIdx.x) >> 5;
    const int lane = threadIdx.x & 31;
    if (gw >= num_users) return;

    const int start = g_offsets[gw];
    const int n     = g_counts[gw];

    // ---- build per-lane mapping (once) ----
    const bool isTT = (lane < 4);
    int s0, s1, s2, s3;          // shuffle source v-indices
    int d0, d1, d2, d3, d4, d5;  // destination offsets in acc row
    int   score_src  = 0;
    float score_mask = 0.f;
    int   score_dst  = 0;

    if (isTT) {
        const int t = lane;
        s0 = 4 * t; s1 = 4 * t + 1; s2 = 4 * t + 2; s3 = 4 * t + 3;
        d0 = TRI(4 * t,     4 * t);
        d1 = TRI(4 * t + 1, 4 * t);
        d2 = TRI(4 * t + 1, 4 * t + 1);
        d3 = TRI(4 * t + 2, 4 * t + 2);
        d4 = TRI(4 * t + 3, 4 * t + 2);
        d5 = TRI(4 * t + 3, 4 * t + 3);
    } else {
        const int c = lane - 4;
        int i0, k0;
        if (c < 4) {                      // diag block lower-left 2x2
            i0 = 4 * c + 2; k0 = 4 * c;
        } else {                          // off-diag block quadrant
            const int c2 = c - 4;
            const int m = c2 >> 2, q = c2 & 3;
            // (A,B) for m = 0..5: (0,1),(0,2),(0,3),(1,2),(1,3),(2,3)
            const int A = (m < 3) ? 0 : ((m < 5) ? 1 : 2);
            const int B = (m < 3) ? (m + 1) : ((m < 5) ? (m - 1) : 3);  // FIXED
            i0 = 4 * B + 2 * (q >> 1);
            k0 = 4 * A + 2 * (q & 1);
        }
        const int i1 = i0 + 1, k1 = k0 + 1;
        s0 = i0; s1 = i1; s2 = k0; s3 = k1;
        d0 = TRI(i0, k0); d1 = TRI(i0, k1);
        d2 = TRI(i1, k0); d3 = TRI(i1, k1);
        d4 = 0; d5 = 0;
        if (lane >= 4 && lane < 20) {     // score carrier
            score_src  = lane - 4;
            score_mask = 1.f;
            score_dst  = NTRI + (lane - 4);
        }
    }

    float a0 = 0.f, a1 = 0.f, a2 = 0.f, a3 = 0.f, a4 = 0.f, a5 = 0.f;
    float asc = 0.f;

    const unsigned FULL = 0xffffffffu;
    for (int t0 = 0; t0 < n; t0 += 32) {
        const int rem = n - t0;
        int2 ob = (lane < rem) ? __ldg(&g_sorted[start + t0 + lane])
                               : make_int2(0, 0);
        const int m = rem < 32 ? rem : 32;
        for (int t = 0; t < m; t++) {
            const int   it = __shfl_sync(FULL, ob.x, t);
            const float r  = __shfl_sync(FULL, __int_as_float(ob.y), t);
            const float vl = __ldg(&V[(it << 4) + (lane & 15)]);
            const float w0 = __shfl_sync(FULL, vl, s0);
            const float w1 = __shfl_sync(FULL, vl, s1);
            const float w2 = __shfl_sync(FULL, vl, s2);
            const float w3 = __shfl_sync(FULL, vl, s3);
            const float ws = __shfl_sync(FULL, vl, score_src);
            if (isTT) {
                a0 += w0 * w0; a1 += w1 * w0; a2 += w1 * w1;
                a3 += w2 * w2; a4 += w3 * w2; a5 += w3 * w3;
            } else {
                a0 += w0 * w2; a1 += w0 * w3;
                a2 += w1 * w2; a3 += w1 * w3;
                asc += r * ws;  // only written back by score-carrier lanes
            }
        }
    }

    float* acc = g_acc + (size_t)gw * ACC_STRIDE;
    if (isTT) {
        acc[d0] = a0; acc[d1] = a1; acc[d2] = a2;
        acc[d3] = a3; acc[d4] = a4; acc[d5] = a5;
    } else {
        acc[d0] = a0; acc[d1] = a1; acc[d2] = a2; acc[d3] = a3;
        if (score_mask != 0.f) acc[score_dst] = asc;
    }
}

// ---------------------------------------------------------------------------
// Phase 3: per-user dense solve (one thread per user, fully unrolled d=16)
// ---------------------------------------------------------------------------
__global__ void __launch_bounds__(128, 2)
solve_kernel(const float* __restrict__ lambdaK,
             const float* __restrict__ muK,
             const float* __restrict__ z,
             float*       __restrict__ out,
             int num_users) {
    int u = blockIdx.x * blockDim.x + threadIdx.x;
    if (u >= num_users) return;

    const float* S = g_acc + (size_t)u * ACC_STRIDE;

    // Q = J * prec * J, packed lower (i >= j):
    //   Q[i][j] = prec[15-i][15-j]; with a=15-i <= b=15-j,
    //   prec[a][b] = lambda[a*16+b] + alpha * outer[b][a]
    float H[NTRI];
#pragma unroll
    for (int i = 0; i < D; i++) {
#pragma unroll
        for (int j = 0; j <= i; j++) {
            const int a = 15 - i, b = 15 - j;   // b >= a
            H[TRI(i, j)] = __ldg(&lambdaK[a * D + b]) + ALPHA_F * S[TRI(b, a)];
        }
    }

    // Reversed rhs: w[i] = rhs[15-i], rhs[a] = alpha*score[a] + (lambda@muK)[a]
    float w[D];
#pragma unroll
    for (int i = 0; i < D; i++) {
        const int a = 15 - i;
        float t = ALPHA_F * S[NTRI + a];
#pragma unroll
        for (int b = 0; b < D; b++) {
            t += __ldg(&lambdaK[a * D + b]) * __ldg(&muK[b]);
        }
        w[i] = t;
    }

    // In-place Cholesky of Q
    float dinv[D];
#pragma unroll
    for (int j = 0; j < D; j++) {
        float s = H[TRI(j, j)];
#pragma unroll
        for (int k = 0; k < j; k++) {
            const float g = H[TRI(j, k)];
            s -= g * g;
        }
        const float sq = sqrtf(s);
        const float rj = 1.0f / sq;
        H[TRI(j, j)] = sq;
        dinv[j] = rj;
#pragma unroll
        for (int i = j + 1; i < D; i++) {
            float t = H[TRI(i, j)];
#pragma unroll
            for (int k = 0; k < j; k++) {
                t -= H[TRI(i, k)] * H[TRI(j, k)];
            }
            H[TRI(i, j)] = t * rj;
        }
    }

    // Solve Q x = w: forward then backward, in place. mu[a] = w[15-a].
#pragma unroll
    for (int i = 0; i < D; i++) {
        float t = w[i];
#pragma unroll
        for (int k = 0; k < i; k++) t -= H[TRI(i, k)] * w[k];
        w[i] = t * dinv[i];
    }
#pragma unroll
    for (int i = D - 1; i >= 0; i--) {
        float t = w[i];
#pragma unroll
        for (int k = D - 1; k > i; k--) t -= H[TRI(k, i)] * w[k];
        w[i] = t * dinv[i];
    }

    // Sample term: L z = J H^{-T} (J z); one backward substitution.
    const float4* zr = reinterpret_cast<const float4*>(z + (size_t)u * D);
    float4 z0 = zr[0], z1 = zr[1], z2 = zr[2], z3 = zr[3];
    float zf[D] = {z0.x, z0.y, z0.z, z0.w, z1.x, z1.y, z1.z, z1.w,
                   z2.x, z2.y, z2.z, z2.w, z3.x, z3.y, z3.z, z3.w};
    float s[D];
#pragma unroll
    for (int i = 0; i < D; i++) s[i] = zf[15 - i];   // Jz
#pragma unroll
    for (int i = D - 1; i >= 0; i--) {
        float t = s[i];
#pragma unroll
        for (int k = D - 1; k > i; k--) t -= H[TRI(k, i)] * s[k];
        s[i] = t * dinv[i];
    }

    // out[a] = mu[a] + (Lz)[a] = w[15-a] + s[15-a]
    float4* o = reinterpret_cast<float4*>(out + (size_t)u * D);
    float r0[D];
#pragma unroll
    for (int a = 0; a < D; a++) r0[a] = w[15 - a] + s[15 - a];
    o[0] = make_float4(r0[0],  r0[1],  r0[2],  r0[3]);
    o[1] = make_float4(r0[4],  r0[5],  r0[6],  r0[7]);
    o[2] = make_float4(r0[8],  r0[9],  r0[10], r0[11]);
    o[3] = make_float4(r0[12], r0[13], r0[14], r0[15]);
}

// ---------------------------------------------------------------------------
extern "C" void kernel_launch(void* const* d_in, const int* in_sizes, int n_in,
                              void* d_out, int out_size) {
    const float* V       = (const float*)d_in[0];
    const float* ratings = (const float*)d_in[1];
    const float* muK     = (const float*)d_in[2];
    const float* lambdaK = (const float*)d_in[3];
    const float* z       = (const float*)d_in[4];
    const int*   uid     = (const int*)d_in[5];
    const int*   iid     = (const int*)d_in[6];

    const int nnz       = in_sizes[5];        // user_ids length
    const int num_users = in_sizes[4] / D;    // z is [U, 16]

    zero_counts_kernel<<<(num_users + 255) / 256, 256>>>(num_users);
    hist_kernel<<<(nnz + 255) / 256, 256>>>(uid, nnz);
    scan_kernel<<<1, 1024>>>(num_users);
    bucket_kernel<<<(nnz + 255) / 256, 256>>>(uid, iid, ratings, nnz);

    const int warps_per_block = 8;                    // 256 threads
    const int accum_blocks = (num_users + warps_per_block - 1) / warps_per_block;
    accum_kernel<<<accum_blocks, 32 * warps_per_block>>>(V, num_users);

    solve_kernel<<<(num_users + 127) / 128, 128>>>(lambdaK, muK, z,
                                                   (float*)d_out, num_users);
}